// round 1
// baseline (speedup 1.0000x reference)
#include <cuda_runtime.h>

#define NB 16384            // batch
#define NPARAM 811
// param offsets within the 811-vector (order: w1,b1,w2,b2,w3,b3,w4,b4)
#define P_W1 0              // 27  = 3 cout * 9 * 1 cin
#define P_B1 27             // 3
#define P_W2 30             // 162 = 6 cout * 9 * 3 cin
#define P_B2 192            // 6
#define P_W3 198            // 162 = 3 cout * 9 * 6 cin
#define P_B3 360            // 3
#define P_W4 363            // 432 = 16 cout * 9 * 3 cin
#define P_B4 795            // 16

// Scratch (param-major [idx][NB] so lane==sample is always a coalesced 128B line)
__device__ float g_h [16  * NB];   // MLP hidden (post-relu layer 2)
__device__ float g_w [NPARAM * NB];// generated per-sample conv params
__device__ float g_p1[507 * NB];   // pooled conv1: 13*13*3
__device__ float g_p2[150 * NB];   // pooled conv2: 5*5*6
__device__ float g_a3[27  * NB];   // relu conv3:   3*3*3

// ---------------------------------------------------------------------------
// Kernel 0: MLP hidden layers h = relu(relu(state@W1+b1)@W2+b2)
// ---------------------------------------------------------------------------
__global__ __launch_bounds__(256) void k_mlp_h(
    const float* __restrict__ state,
    const float* __restrict__ W1, const float* __restrict__ b1,
    const float* __restrict__ W2, const float* __restrict__ b2)
{
    int b = blockIdx.x * 256 + threadIdx.x;
    float st[16];
    const float4* sp = reinterpret_cast<const float4*>(state + b * 16);
#pragma unroll
    for (int q = 0; q < 4; q++) {
        float4 v = sp[q];
        st[4*q+0] = v.x; st[4*q+1] = v.y; st[4*q+2] = v.z; st[4*q+3] = v.w;
    }
    float h1[16];
#pragma unroll
    for (int i = 0; i < 16; i++) h1[i] = __ldg(&b1[i]);
#pragma unroll
    for (int k = 0; k < 16; k++) {
        float s = st[k];
#pragma unroll
        for (int i = 0; i < 16; i++) h1[i] += s * __ldg(&W1[k*16 + i]);
    }
#pragma unroll
    for (int i = 0; i < 16; i++) h1[i] = fmaxf(h1[i], 0.f);

    float h2[16];
#pragma unroll
    for (int i = 0; i < 16; i++) h2[i] = __ldg(&b2[i]);
#pragma unroll
    for (int k = 0; k < 16; k++) {
        float s = h1[k];
#pragma unroll
        for (int i = 0; i < 16; i++) h2[i] += s * __ldg(&W2[k*16 + i]);
    }
#pragma unroll
    for (int i = 0; i < 16; i++) g_h[i*NB + b] = fmaxf(h2[i], 0.f);
}

// ---------------------------------------------------------------------------
// Kernel 1: MLP layer 3 -> g_w[j][b] = b3[j] + sum_k h[k][b]*W3[k][j]
// Block: 32 samples x 8 j-rows (256 thr). Each block covers 64 j's.
// W3 tile staged in smem; float4 broadcast LDS -> 4 FMA per LDS.
// ---------------------------------------------------------------------------
__global__ __launch_bounds__(256) void k_mlp3(
    const float* __restrict__ W3, const float* __restrict__ b3)
{
    __shared__ float W3s[16 * 64];
    __shared__ float b3s[64];
    __shared__ float hs[16 * 33];

    int tid = threadIdx.x;
    int j0  = blockIdx.y * 64;
    int b0  = blockIdx.x * 32;

    for (int idx = tid; idx < 16 * 64; idx += 256) {
        int k = idx >> 6, jj = idx & 63;
        int j = j0 + jj;
        W3s[idx] = (j < NPARAM) ? W3[k * NPARAM + j] : 0.f;
    }
    if (tid < 64) {
        int j = j0 + tid;
        b3s[tid] = (j < NPARAM) ? b3[j] : 0.f;
    }
    for (int idx = tid; idx < 16 * 32; idx += 256) {
        int k = idx >> 5, s = idx & 31;
        hs[k * 33 + s] = g_h[k * NB + b0 + s];
    }
    __syncthreads();

    int s  = tid & 31;
    int jr = tid >> 5;           // 0..7
    int b  = b0 + s;

    float h[16];
#pragma unroll
    for (int k = 0; k < 16; k++) h[k] = hs[k * 33 + s];

    float acc[8];
#pragma unroll
    for (int i = 0; i < 8; i++) acc[i] = b3s[jr * 8 + i];

#pragma unroll
    for (int k = 0; k < 16; k++) {
        float hk = h[k];
        float4 wA = *reinterpret_cast<const float4*>(&W3s[k * 64 + jr * 8]);
        float4 wB = *reinterpret_cast<const float4*>(&W3s[k * 64 + jr * 8 + 4]);
        acc[0] += hk * wA.x; acc[1] += hk * wA.y;
        acc[2] += hk * wA.z; acc[3] += hk * wA.w;
        acc[4] += hk * wB.x; acc[5] += hk * wB.y;
        acc[6] += hk * wB.z; acc[7] += hk * wB.w;
    }
#pragma unroll
    for (int i = 0; i < 8; i++) {
        int j = j0 + jr * 8 + i;
        if (j < NPARAM) g_w[j * NB + b] = acc[i];
    }
}

// ---------------------------------------------------------------------------
// Kernel 2: conv1(3x3, 1->3) + relu + maxpool2. One pooled row per blockIdx.y.
// Rolling 4x4 register window over the image; weights in registers.
// ---------------------------------------------------------------------------
__global__ __launch_bounds__(128) void k_conv1(const float* __restrict__ img)
{
    int b  = blockIdx.x * 128 + threadIdx.x;
    int pr = blockIdx.y;            // pooled row 0..12

    float wt[27], bias[3];
#pragma unroll
    for (int p = 0; p < 27; p++) wt[p] = g_w[(P_W1 + p) * NB + b];
#pragma unroll
    for (int c = 0; c < 3; c++)  bias[c] = g_w[(P_B1 + c) * NB + b];

    const float* imrow = img + (2 * pr * 28) * NB + b;   // image rows 2pr..2pr+3

    float win[4][4];
#pragma unroll
    for (int i = 0; i < 4; i++)
#pragma unroll
        for (int c = 0; c < 4; c++)
            win[i][c] = imrow[(i * 28 + c) * NB];

#pragma unroll
    for (int pc = 0; pc < 13; pc++) {
        if (pc > 0) {
#pragma unroll
            for (int i = 0; i < 4; i++) {
                win[i][0] = win[i][2];
                win[i][1] = win[i][3];
                win[i][2] = imrow[(i * 28 + 2 * pc + 2) * NB];
                win[i][3] = imrow[(i * 28 + 2 * pc + 3) * NB];
            }
        }
        float acc[2][2][3];
#pragma unroll
        for (int dr = 0; dr < 2; dr++)
#pragma unroll
            for (int dc = 0; dc < 2; dc++)
#pragma unroll
                for (int co = 0; co < 3; co++) acc[dr][dc][co] = bias[co];

#pragma unroll
        for (int ky = 0; ky < 3; ky++)
#pragma unroll
            for (int kx = 0; kx < 3; kx++) {
#pragma unroll
                for (int dr = 0; dr < 2; dr++)
#pragma unroll
                    for (int dc = 0; dc < 2; dc++) {
                        float v = win[dr + ky][dc + kx];
#pragma unroll
                        for (int co = 0; co < 3; co++)
                            acc[dr][dc][co] += v * wt[co * 9 + ky * 3 + kx];
                    }
            }
#pragma unroll
        for (int co = 0; co < 3; co++) {
            float m = fmaxf(fmaxf(acc[0][0][co], acc[0][1][co]),
                            fmaxf(acc[1][0][co], acc[1][1][co]));
            g_p1[((pr * 13 + pc) * 3 + co) * NB + b] = fmaxf(m, 0.f);
        }
    }
}

// ---------------------------------------------------------------------------
// Kernel 3: conv2(3x3, 3->6) + relu + maxpool2. blockIdx.y = pooled row (0..4),
// blockIdx.z = cout half (3 couts each, so 84 weight regs fit).
// Rolling 4(row)x4(col)x3(cin) register window over pooled1.
// ---------------------------------------------------------------------------
__global__ __launch_bounds__(128) void k_conv2()
{
    int b   = blockIdx.x * 128 + threadIdx.x;
    int p2  = blockIdx.y;           // 0..4
    int coh = blockIdx.z;           // 0..1

    float wt[3][27], bias[3];
#pragma unroll
    for (int c = 0; c < 3; c++) {
        int co = coh * 3 + c;
#pragma unroll
        for (int t = 0; t < 27; t++)
            wt[c][t] = g_w[(P_W2 + co * 27 + t) * NB + b];
        bias[c] = g_w[(P_B2 + co) * NB + b];
    }

    const float* p1 = g_p1 + (2 * p2 * 13 * 3) * NB + b;  // pooled1 rows 2p2..2p2+3

    float win[4][4][3];
#pragma unroll
    for (int i = 0; i < 4; i++)
#pragma unroll
        for (int cc = 0; cc < 4; cc++)
#pragma unroll
            for (int ci = 0; ci < 3; ci++)
                win[i][cc][ci] = p1[((i * 13 + cc) * 3 + ci) * NB];

#pragma unroll
    for (int pc = 0; pc < 5; pc++) {
        if (pc > 0) {
#pragma unroll
            for (int i = 0; i < 4; i++)
#pragma unroll
                for (int ci = 0; ci < 3; ci++) {
                    win[i][0][ci] = win[i][2][ci];
                    win[i][1][ci] = win[i][3][ci];
                    win[i][2][ci] = p1[((i * 13 + 2 * pc + 2) * 3 + ci) * NB];
                    win[i][3][ci] = p1[((i * 13 + 2 * pc + 3) * 3 + ci) * NB];
                }
        }
        float acc[2][2][3];
#pragma unroll
        for (int dr = 0; dr < 2; dr++)
#pragma unroll
            for (int dc = 0; dc < 2; dc++)
#pragma unroll
                for (int c = 0; c < 3; c++) acc[dr][dc][c] = bias[c];

#pragma unroll
        for (int ky = 0; ky < 3; ky++)
#pragma unroll
            for (int kx = 0; kx < 3; kx++)
#pragma unroll
                for (int ci = 0; ci < 3; ci++) {
#pragma unroll
                    for (int dr = 0; dr < 2; dr++)
#pragma unroll
                        for (int dc = 0; dc < 2; dc++) {
                            float v = win[dr + ky][dc + kx][ci];
#pragma unroll
                            for (int c = 0; c < 3; c++)
                                acc[dr][dc][c] += v * wt[c][(ky * 3 + kx) * 3 + ci];
                        }
                }
#pragma unroll
        for (int c = 0; c < 3; c++) {
            float m = fmaxf(fmaxf(acc[0][0][c], acc[0][1][c]),
                            fmaxf(acc[1][0][c], acc[1][1][c]));
            g_p2[((p2 * 5 + pc) * 6 + coh * 3 + c) * NB + b] = fmaxf(m, 0.f);
        }
    }
}

// ---------------------------------------------------------------------------
// Kernel 4: conv3(3x3, 6->3) + relu. blockIdx.y = cout (0..2).
// ---------------------------------------------------------------------------
__global__ __launch_bounds__(128) void k_conv3()
{
    int b  = blockIdx.x * 128 + threadIdx.x;
    int co = blockIdx.y;           // 0..2

    float wt[54];
#pragma unroll
    for (int t = 0; t < 54; t++) wt[t] = g_w[(P_W3 + co * 54 + t) * NB + b];
    float bias = g_w[(P_B3 + co) * NB + b];

#pragma unroll
    for (int r = 0; r < 3; r++) {
        float win[3][5][6];
#pragma unroll
        for (int i = 0; i < 3; i++)
#pragma unroll
            for (int c = 0; c < 5; c++)
#pragma unroll
                for (int ci = 0; ci < 6; ci++)
                    win[i][c][ci] = g_p2[(((r + i) * 5 + c) * 6 + ci) * NB + b];

#pragma unroll
        for (int oc = 0; oc < 3; oc++) {
            float acc = bias;
#pragma unroll
            for (int ky = 0; ky < 3; ky++)
#pragma unroll
                for (int kx = 0; kx < 3; kx++)
#pragma unroll
                    for (int ci = 0; ci < 6; ci++)
                        acc += win[ky][oc + kx][ci] * wt[(ky * 3 + kx) * 6 + ci];
            g_a3[((r * 3 + oc) * 3 + co) * NB + b] = fmaxf(acc, 0.f);
        }
    }
}

// ---------------------------------------------------------------------------
// Kernel 5: conv4(3x3, 3->16, output 1x1) + residual. blockIdx.y = cout (0..15).
// ---------------------------------------------------------------------------
__global__ __launch_bounds__(128) void k_conv4(
    const float* __restrict__ state, float* __restrict__ out)
{
    int b  = blockIdx.x * 128 + threadIdx.x;
    int co = blockIdx.y;           // 0..15

    float acc = g_w[(P_B4 + co) * NB + b];
#pragma unroll
    for (int t = 0; t < 27; t++)
        acc += g_a3[t * NB + b] * g_w[(P_W4 + co * 27 + t) * NB + b];

    out[b * 16 + co] = state[b * 16 + co] + acc;
}

// ---------------------------------------------------------------------------
extern "C" void kernel_launch(void* const* d_in, const int* in_sizes, int n_in,
                              void* d_out, int out_size)
{
    const float* image = (const float*)d_in[0];
    const float* state = (const float*)d_in[1];
    const float* W1    = (const float*)d_in[2];
    const float* b1    = (const float*)d_in[3];
    const float* W2    = (const float*)d_in[4];
    const float* b2    = (const float*)d_in[5];
    const float* W3    = (const float*)d_in[6];
    const float* b3    = (const float*)d_in[7];
    float* out = (float*)d_out;

    k_mlp_h<<<NB / 256, 256>>>(state, W1, b1, W2, b2);
    k_mlp3 <<<dim3(NB / 32, 13), 256>>>(W3, b3);
    k_conv1<<<dim3(NB / 128, 13), 128>>>(image);
    k_conv2<<<dim3(NB / 128, 5, 2), 128>>>();
    k_conv3<<<dim3(NB / 128, 3), 128>>>();
    k_conv4<<<dim3(NB / 128, 16), 128>>>(state, out);
}

// round 3
// speedup vs baseline: 1.0955x; 1.0955x over previous
#include <cuda_runtime.h>

#define NB 16384            // batch
#define NPARAM 811
// param offsets within the 811-vector (order: w1,b1,w2,b2,w3,b3,w4,b4)
#define P_W1 0              // 27  = 3 cout * 9 * 1 cin
#define P_B1 27             // 3
#define P_W2 30             // 162 = 6 cout * 9 * 3 cin
#define P_B2 192            // 6
#define P_W3 198            // 162 = 3 cout * 9 * 6 cin
#define P_B3 360            // 3
#define P_W4 363            // 432 = 16 cout * 9 * 3 cin
#define P_B4 795            // 16

// Scratch (param-major [idx][NB]: lane-pair==sample-pair -> aligned float2)
__device__ float g_h [16  * NB];   // MLP hidden (post-relu layer 2)
__device__ float g_w [NPARAM * NB];// generated per-sample conv params
__device__ float g_p1[507 * NB];   // pooled conv1: 13*13*3
__device__ float g_p2[150 * NB];   // pooled conv2: 5*5*6
__device__ float g_a3[27  * NB];   // relu conv3:   3*3*3

// ---- packed fp32x2 FMA (FFMA2) ------------------------------------------
union F2U { float2 f; unsigned long long u; };
__device__ __forceinline__ float2 ffma2(float2 a, float2 b, float2 c) {
    F2U A, B, C, D; A.f = a; B.f = b; C.f = c;
    asm("fma.rn.f32x2 %0, %1, %2, %3;" : "=l"(D.u) : "l"(A.u), "l"(B.u), "l"(C.u));
    return D.f;
}
__device__ __forceinline__ float2 ld2(const float* p) {
    return *reinterpret_cast<const float2*>(p);
}
__device__ __forceinline__ void st2(float* p, float2 v) {
    *reinterpret_cast<float2*>(p) = v;
}
__device__ __forceinline__ float2 max2(float2 a, float2 b) {
    return make_float2(fmaxf(a.x, b.x), fmaxf(a.y, b.y));
}
__device__ __forceinline__ float2 relu2(float2 a) {
    return make_float2(fmaxf(a.x, 0.f), fmaxf(a.y, 0.f));
}

// ---------------------------------------------------------------------------
// Kernel 0: MLP hidden layers h = relu(relu(state@W1+b1)@W2+b2)  (scalar; tiny)
// ---------------------------------------------------------------------------
__global__ __launch_bounds__(256) void k_mlp_h(
    const float* __restrict__ state,
    const float* __restrict__ W1, const float* __restrict__ b1,
    const float* __restrict__ W2, const float* __restrict__ b2)
{
    int b = blockIdx.x * 256 + threadIdx.x;
    float st[16];
    const float4* sp = reinterpret_cast<const float4*>(state + b * 16);
#pragma unroll
    for (int q = 0; q < 4; q++) {
        float4 v = sp[q];
        st[4*q+0] = v.x; st[4*q+1] = v.y; st[4*q+2] = v.z; st[4*q+3] = v.w;
    }
    float h1[16];
#pragma unroll
    for (int i = 0; i < 16; i++) h1[i] = __ldg(&b1[i]);
#pragma unroll
    for (int k = 0; k < 16; k++) {
        float s = st[k];
#pragma unroll
        for (int i = 0; i < 16; i++) h1[i] += s * __ldg(&W1[k*16 + i]);
    }
#pragma unroll
    for (int i = 0; i < 16; i++) h1[i] = fmaxf(h1[i], 0.f);

    float h2[16];
#pragma unroll
    for (int i = 0; i < 16; i++) h2[i] = __ldg(&b2[i]);
#pragma unroll
    for (int k = 0; k < 16; k++) {
        float s = h1[k];
#pragma unroll
        for (int i = 0; i < 16; i++) h2[i] += s * __ldg(&W2[k*16 + i]);
    }
#pragma unroll
    for (int i = 0; i < 16; i++) g_h[i*NB + b] = fmaxf(h2[i], 0.f);
}

// ---------------------------------------------------------------------------
// Kernel 1: MLP layer 3 (packed). Block: 32 sample-pairs x 8 j-rows (256 thr),
// covers 64 samples x 64 j per block. W3 staged in smem pre-duplicated {w,w}.
// ---------------------------------------------------------------------------
__global__ __launch_bounds__(256) void k_mlp3(
    const float* __restrict__ W3, const float* __restrict__ b3)
{
    __shared__ float2 W3s[16 * 64];   // duplicated weights
    __shared__ float  b3s[64];

    int tid = threadIdx.x;
    int j0  = blockIdx.y * 64;
    int b0  = blockIdx.x * 64;        // 64 samples (32 pairs)

    for (int idx = tid; idx < 16 * 64; idx += 256) {
        int k = idx >> 6, jj = idx & 63;
        int j = j0 + jj;
        float w = (j < NPARAM) ? W3[k * NPARAM + j] : 0.f;
        W3s[idx] = make_float2(w, w);
    }
    if (tid < 64) {
        int j = j0 + tid;
        b3s[tid] = (j < NPARAM) ? b3[j] : 0.f;
    }
    __syncthreads();

    int s  = tid & 31;
    int jr = tid >> 5;                // 0..7
    int b  = b0 + 2 * s;

    float2 h[16];
#pragma unroll
    for (int k = 0; k < 16; k++) h[k] = ld2(&g_h[k * NB + b]);

    float2 acc[8];
#pragma unroll
    for (int i = 0; i < 8; i++) {
        float bb = b3s[jr * 8 + i];
        acc[i] = make_float2(bb, bb);
    }
#pragma unroll
    for (int k = 0; k < 16; k++) {
#pragma unroll
        for (int i = 0; i < 8; i++)
            acc[i] = ffma2(h[k], W3s[k * 64 + jr * 8 + i], acc[i]);
    }
#pragma unroll
    for (int i = 0; i < 8; i++) {
        int j = j0 + jr * 8 + i;
        if (j < NPARAM) st2(&g_w[j * NB + b], acc[i]);
    }
}

// ---------------------------------------------------------------------------
// Kernel 2: conv1(3x3,1->3)+relu+maxpool2, packed pair/thread.
// ---------------------------------------------------------------------------
__global__ __launch_bounds__(128) void k_conv1(const float* __restrict__ img)
{
    int b  = (blockIdx.x * 128 + threadIdx.x) * 2;
    int pr = blockIdx.y;            // pooled row 0..12

    float2 wt[27], bias[3];
#pragma unroll
    for (int p = 0; p < 27; p++) wt[p] = ld2(&g_w[(P_W1 + p) * NB + b]);
#pragma unroll
    for (int c = 0; c < 3; c++)  bias[c] = ld2(&g_w[(P_B1 + c) * NB + b]);

    const float* imrow = img + (2 * pr * 28) * NB + b;   // rows 2pr..2pr+3

    float2 win[4][4];
#pragma unroll
    for (int i = 0; i < 4; i++)
#pragma unroll
        for (int c = 0; c < 4; c++)
            win[i][c] = ld2(&imrow[(i * 28 + c) * NB]);

#pragma unroll
    for (int pc = 0; pc < 13; pc++) {
        if (pc > 0) {
#pragma unroll
            for (int i = 0; i < 4; i++) {
                win[i][0] = win[i][2];
                win[i][1] = win[i][3];
                win[i][2] = ld2(&imrow[(i * 28 + 2 * pc + 2) * NB]);
                win[i][3] = ld2(&imrow[(i * 28 + 2 * pc + 3) * NB]);
            }
        }
        float2 acc[2][2][3];
#pragma unroll
        for (int dr = 0; dr < 2; dr++)
#pragma unroll
            for (int dc = 0; dc < 2; dc++)
#pragma unroll
                for (int co = 0; co < 3; co++) acc[dr][dc][co] = bias[co];

#pragma unroll
        for (int ky = 0; ky < 3; ky++)
#pragma unroll
            for (int kx = 0; kx < 3; kx++) {
#pragma unroll
                for (int dr = 0; dr < 2; dr++)
#pragma unroll
                    for (int dc = 0; dc < 2; dc++) {
                        float2 v = win[dr + ky][dc + kx];
#pragma unroll
                        for (int co = 0; co < 3; co++)
                            acc[dr][dc][co] = ffma2(v, wt[co * 9 + ky * 3 + kx],
                                                    acc[dr][dc][co]);
                    }
            }
#pragma unroll
        for (int co = 0; co < 3; co++) {
            float2 m = max2(max2(acc[0][0][co], acc[0][1][co]),
                            max2(acc[1][0][co], acc[1][1][co]));
            st2(&g_p1[((pr * 13 + pc) * 3 + co) * NB + b], relu2(m));
        }
    }
}

// ---------------------------------------------------------------------------
// Kernel 3: conv2(3x3,3->6)+relu+maxpool2, packed. blockIdx.z = cout pair
// (3 blocks of 2 couts -> 108 weight regs + 96 window regs).
// ---------------------------------------------------------------------------
__global__ __launch_bounds__(128) void k_conv2()
{
    int b   = (blockIdx.x * 128 + threadIdx.x) * 2;
    int p2  = blockIdx.y;           // 0..4
    int coh = blockIdx.z;           // 0..2 -> couts 2*coh, 2*coh+1

    float2 wt[2][27], bias[2];
#pragma unroll
    for (int c = 0; c < 2; c++) {
        int co = coh * 2 + c;
#pragma unroll
        for (int t = 0; t < 27; t++)
            wt[c][t] = ld2(&g_w[(P_W2 + co * 27 + t) * NB + b]);
        bias[c] = ld2(&g_w[(P_B2 + co) * NB + b]);
    }

    const float* p1 = g_p1 + (2 * p2 * 13 * 3) * NB + b;  // rows 2p2..2p2+3

    float2 win[4][4][3];
#pragma unroll
    for (int i = 0; i < 4; i++)
#pragma unroll
        for (int cc = 0; cc < 4; cc++)
#pragma unroll
            for (int ci = 0; ci < 3; ci++)
                win[i][cc][ci] = ld2(&p1[((i * 13 + cc) * 3 + ci) * NB]);

#pragma unroll
    for (int pc = 0; pc < 5; pc++) {
        if (pc > 0) {
#pragma unroll
            for (int i = 0; i < 4; i++)
#pragma unroll
                for (int ci = 0; ci < 3; ci++) {
                    win[i][0][ci] = win[i][2][ci];
                    win[i][1][ci] = win[i][3][ci];
                    win[i][2][ci] = ld2(&p1[((i * 13 + 2 * pc + 2) * 3 + ci) * NB]);
                    win[i][3][ci] = ld2(&p1[((i * 13 + 2 * pc + 3) * 3 + ci) * NB]);
                }
        }
        float2 acc[2][2][2];
#pragma unroll
        for (int dr = 0; dr < 2; dr++)
#pragma unroll
            for (int dc = 0; dc < 2; dc++)
#pragma unroll
                for (int c = 0; c < 2; c++) acc[dr][dc][c] = bias[c];

#pragma unroll
        for (int ky = 0; ky < 3; ky++)
#pragma unroll
            for (int kx = 0; kx < 3; kx++)
#pragma unroll
                for (int ci = 0; ci < 3; ci++) {
#pragma unroll
                    for (int dr = 0; dr < 2; dr++)
#pragma unroll
                        for (int dc = 0; dc < 2; dc++) {
                            float2 v = win[dr + ky][dc + kx][ci];
#pragma unroll
                            for (int c = 0; c < 2; c++)
                                acc[dr][dc][c] = ffma2(v, wt[c][(ky * 3 + kx) * 3 + ci],
                                                       acc[dr][dc][c]);
                        }
                }
#pragma unroll
        for (int c = 0; c < 2; c++) {
            float2 m = max2(max2(acc[0][0][c], acc[0][1][c]),
                            max2(acc[1][0][c], acc[1][1][c]));
            st2(&g_p2[((p2 * 5 + pc) * 6 + coh * 2 + c) * NB + b], relu2(m));
        }
    }
}

// ---------------------------------------------------------------------------
// Kernel 4: conv3(3x3,6->3)+relu, packed. blockIdx.y = cout; per output row
// loop over two ci-halves so window (45 f2) + half-weights (27 f2) fit regs.
// ---------------------------------------------------------------------------
__global__ __launch_bounds__(128) void k_conv3()
{
    int b  = (blockIdx.x * 128 + threadIdx.x) * 2;
    int co = blockIdx.y;           // 0..2

    float2 bias = ld2(&g_w[(P_B3 + co) * NB + b]);

#pragma unroll
    for (int r = 0; r < 3; r++) {
        float2 acc[3];
#pragma unroll
        for (int oc = 0; oc < 3; oc++) acc[oc] = bias;

#pragma unroll
        for (int h = 0; h < 2; h++) {
            float2 wt[27];
#pragma unroll
            for (int t = 0; t < 9; t++)
#pragma unroll
                for (int c3 = 0; c3 < 3; c3++)
                    wt[t * 3 + c3] =
                        ld2(&g_w[(P_W3 + co * 54 + t * 6 + h * 3 + c3) * NB + b]);

            float2 win[3][5][3];
#pragma unroll
            for (int i = 0; i < 3; i++)
#pragma unroll
                for (int c = 0; c < 5; c++)
#pragma unroll
                    for (int c3 = 0; c3 < 3; c3++)
                        win[i][c][c3] =
                            ld2(&g_p2[(((r + i) * 5 + c) * 6 + h * 3 + c3) * NB + b]);

#pragma unroll
            for (int oc = 0; oc < 3; oc++)
#pragma unroll
                for (int ky = 0; ky < 3; ky++)
#pragma unroll
                    for (int kx = 0; kx < 3; kx++)
#pragma unroll
                        for (int c3 = 0; c3 < 3; c3++)
                            acc[oc] = ffma2(win[ky][oc + kx][c3],
                                            wt[(ky * 3 + kx) * 3 + c3], acc[oc]);
        }
#pragma unroll
        for (int oc = 0; oc < 3; oc++)
            st2(&g_a3[((r * 3 + oc) * 3 + co) * NB + b], relu2(acc[oc]));
    }
}

// ---------------------------------------------------------------------------
// Kernel 5: conv4(3x3,3->16, output 1x1) + residual, packed.
// ---------------------------------------------------------------------------
__global__ __launch_bounds__(128) void k_conv4(
    const float* __restrict__ state, float* __restrict__ out)
{
    int b  = (blockIdx.x * 128 + threadIdx.x) * 2;
    int co = blockIdx.y;           // 0..15

    float2 acc = ld2(&g_w[(P_B4 + co) * NB + b]);
#pragma unroll
    for (int t = 0; t < 27; t++)
        acc = ffma2(ld2(&g_a3[t * NB + b]),
                    ld2(&g_w[(P_W4 + co * 27 + t) * NB + b]), acc);

    out[b * 16 + co]       = state[b * 16 + co]       + acc.x;
    out[(b + 1) * 16 + co] = state[(b + 1) * 16 + co] + acc.y;
}

// ---------------------------------------------------------------------------
extern "C" void kernel_launch(void* const* d_in, const int* in_sizes, int n_in,
                              void* d_out, int out_size)
{
    const float* image = (const float*)d_in[0];
    const float* state = (const float*)d_in[1];
    const float* W1    = (const float*)d_in[2];
    const float* b1    = (const float*)d_in[3];
    const float* W2    = (const float*)d_in[4];
    const float* b2    = (const float*)d_in[5];
    const float* W3    = (const float*)d_in[6];
    const float* b3    = (const float*)d_in[7];
    float* out = (float*)d_out;

    k_mlp_h<<<NB / 256, 256>>>(state, W1, b1, W2, b2);
    k_mlp3 <<<dim3(NB / 64, 13), 256>>>(W3, b3);
    k_conv1<<<dim3(NB / 256, 13), 128>>>(image);
    k_conv2<<<dim3(NB / 256, 5, 3), 128>>>();
    k_conv3<<<dim3(NB / 256, 3), 128>>>();
    k_conv4<<<dim3(NB / 256, 16), 128>>>(state, out);
}